// round 1
// baseline (speedup 1.0000x reference)
#include <cuda_runtime.h>
#include <math.h>

#define D_MODEL 768
#define N_HEADS 12
#define D_KH    64
#define B_      2
#define S_      2048
#define M_TOT   (B_ * S_)      // 4096 tokens
#define LN_EPS  1e-5f

// ---------------- scratch (allocation-free: __device__ globals) ----------------
__device__ float g_Q[(size_t)M_TOT * D_MODEL];
__device__ float g_K[(size_t)M_TOT * D_MODEL];
__device__ float g_V[(size_t)M_TOT * D_MODEL];
__device__ float g_O[(size_t)M_TOT * D_MODEL];   // attn @ V, merged heads
__device__ float g_P[(size_t)M_TOT * D_MODEL];   // output projection

// =====================================================================
// GEMM (NT): C[m,n] = sum_k A[m,k] * W[n,k] + bias[n]
// A: [M,768] row-major, W: [768,768] row-major. Tile 64x64x16, 256 thr, 4x4/thread.
// grid: (M/64, 768/64)
// =====================================================================
__global__ void gemm_nt_bias(const float* __restrict__ A,
                             const float* __restrict__ W,
                             const float* __restrict__ bias,
                             float* __restrict__ C)
{
    const int m0 = blockIdx.x * 64;
    const int n0 = blockIdx.y * 64;
    __shared__ float As[64][17];
    __shared__ float Ws[64][17];
    float acc[4][4] = {};
    const int tid = threadIdx.x;
    const int tx = tid & 15, ty = tid >> 4;

    for (int k0 = 0; k0 < 768; k0 += 16) {
        #pragma unroll
        for (int i = 0; i < 4; i++) {
            int e = tid + i * 256;
            int r = e >> 4, c = e & 15;
            As[r][c] = A[(size_t)(m0 + r) * 768 + k0 + c];
            Ws[r][c] = W[(size_t)(n0 + r) * 768 + k0 + c];
        }
        __syncthreads();
        #pragma unroll
        for (int kk = 0; kk < 16; kk++) {
            float a[4], b[4];
            #pragma unroll
            for (int i = 0; i < 4; i++) a[i] = As[ty * 4 + i][kk];
            #pragma unroll
            for (int j = 0; j < 4; j++) b[j] = Ws[tx * 4 + j][kk];
            #pragma unroll
            for (int i = 0; i < 4; i++)
                #pragma unroll
                for (int j = 0; j < 4; j++)
                    acc[i][j] += a[i] * b[j];
        }
        __syncthreads();
    }
    #pragma unroll
    for (int i = 0; i < 4; i++)
        #pragma unroll
        for (int j = 0; j < 4; j++)
            C[(size_t)(m0 + ty * 4 + i) * 768 + n0 + tx * 4 + j] =
                acc[i][j] + bias[n0 + tx * 4 + j];
}

// =====================================================================
// Scores: attn_raw[bh, q, k] = (Q_bh[q,:] . K_bh[k,:]) * 0.125
// Skips fully-masked tiles (kt > qt). Softmax applies the causal mask,
// so garbage in the skipped region is never used.
// grid: (S/64, S/64, B*H)
// =====================================================================
__global__ void scores_kernel(const float* __restrict__ Q,
                              const float* __restrict__ Kp,
                              float* __restrict__ attn)
{
    const int qt = blockIdx.x;
    const int kt = blockIdx.y;
    if (kt > qt) return;                       // fully masked tile
    const int bh = blockIdx.z;
    const int b = bh / N_HEADS, h = bh % N_HEADS;
    const int q0 = qt * 64, k0 = kt * 64;

    const float* Qb = Q + (size_t)(b * S_) * D_MODEL + h * D_KH;
    const float* Kb = Kp + (size_t)(b * S_) * D_MODEL + h * D_KH;

    __shared__ float Qs[64][17];
    __shared__ float Ks[64][17];
    float acc[4][4] = {};
    const int tid = threadIdx.x;
    const int tx = tid & 15, ty = tid >> 4;

    for (int kk0 = 0; kk0 < D_KH; kk0 += 16) {
        #pragma unroll
        for (int i = 0; i < 4; i++) {
            int e = tid + i * 256;
            int r = e >> 4, c = e & 15;
            Qs[r][c] = Qb[(size_t)(q0 + r) * D_MODEL + kk0 + c];
            Ks[r][c] = Kb[(size_t)(k0 + r) * D_MODEL + kk0 + c];
        }
        __syncthreads();
        #pragma unroll
        for (int kk = 0; kk < 16; kk++) {
            float a[4], b2[4];
            #pragma unroll
            for (int i = 0; i < 4; i++) a[i] = Qs[ty * 4 + i][kk];
            #pragma unroll
            for (int j = 0; j < 4; j++) b2[j] = Ks[tx * 4 + j][kk];
            #pragma unroll
            for (int i = 0; i < 4; i++)
                #pragma unroll
                for (int j = 0; j < 4; j++)
                    acc[i][j] += a[i] * b2[j];
        }
        __syncthreads();
    }
    float* out = attn + ((size_t)bh * S_ + q0) * S_ + k0;
    #pragma unroll
    for (int i = 0; i < 4; i++)
        #pragma unroll
        for (int j = 0; j < 4; j++)
            out[(size_t)(ty * 4 + i) * S_ + tx * 4 + j] = acc[i][j] * 0.125f;
}

// =====================================================================
// Row softmax with causal mask applied in-kernel (masked -> 0).
// grid: (S, B*H), 256 threads, 8 elements/thread
// =====================================================================
__global__ void softmax_kernel(float* __restrict__ attn)
{
    const int q  = blockIdx.x;
    const int bh = blockIdx.y;
    float* row = attn + ((size_t)bh * S_ + q) * S_;
    const int tid = threadIdx.x;

    float vals[8];
    float m = -INFINITY;
    #pragma unroll
    for (int i = 0; i < 8; i++) {
        int c = tid + i * 256;
        float v = (c <= q) ? row[c] : -INFINITY;
        vals[i] = v;
        m = fmaxf(m, v);
    }
    __shared__ float red[256];
    red[tid] = m; __syncthreads();
    for (int s = 128; s > 0; s >>= 1) {
        if (tid < s) red[tid] = fmaxf(red[tid], red[tid + s]);
        __syncthreads();
    }
    m = red[0];
    __syncthreads();

    float sum = 0.f;
    #pragma unroll
    for (int i = 0; i < 8; i++) {
        float e = __expf(vals[i] - m);   // exp(-inf) -> 0 for masked
        vals[i] = e;
        sum += e;
    }
    red[tid] = sum; __syncthreads();
    for (int s = 128; s > 0; s >>= 1) {
        if (tid < s) red[tid] += red[tid + s];
        __syncthreads();
    }
    const float inv = 1.0f / red[0];
    #pragma unroll
    for (int i = 0; i < 8; i++) {
        int c = tid + i * 256;
        row[c] = vals[i] * inv;
    }
}

// =====================================================================
// PV: O_bh[q, :] = sum_k attn[bh,q,k] * V_bh[k, :]   (N = 64 head dim)
// Causal: attn is zero for k > q, so loop only to the tile's last row.
// grid: (S/64, B*H)
// =====================================================================
__global__ void pv_kernel(const float* __restrict__ attn,
                          const float* __restrict__ V,
                          float* __restrict__ O)
{
    const int qt = blockIdx.x;
    const int bh = blockIdx.y;
    const int b = bh / N_HEADS, h = bh % N_HEADS;
    const int q0 = qt * 64;

    const float* Arow = attn + ((size_t)bh * S_ + q0) * S_;
    const float* Vb = V + (size_t)(b * S_) * D_MODEL + h * D_KH;

    __shared__ float As[64][17];
    __shared__ float Bs[16][65];
    float acc[4][4] = {};
    const int tid = threadIdx.x;
    const int tx = tid & 15, ty = tid >> 4;
    const int kmax = q0 + 64;             // beyond this attn == 0

    for (int k0 = 0; k0 < kmax; k0 += 16) {
        #pragma unroll
        for (int i = 0; i < 4; i++) {
            int e = tid + i * 256;
            int r = e >> 4, c = e & 15;
            As[r][c] = Arow[(size_t)r * S_ + k0 + c];
        }
        #pragma unroll
        for (int i = 0; i < 4; i++) {
            int e = tid + i * 256;
            int r = e >> 6, c = e & 63;
            Bs[r][c] = Vb[(size_t)(k0 + r) * D_MODEL + c];
        }
        __syncthreads();
        #pragma unroll
        for (int kk = 0; kk < 16; kk++) {
            float a[4], b2[4];
            #pragma unroll
            for (int i = 0; i < 4; i++) a[i] = As[ty * 4 + i][kk];
            #pragma unroll
            for (int j = 0; j < 4; j++) b2[j] = Bs[kk][tx * 4 + j];
            #pragma unroll
            for (int i = 0; i < 4; i++)
                #pragma unroll
                for (int j = 0; j < 4; j++)
                    acc[i][j] += a[i] * b2[j];
        }
        __syncthreads();
    }
    float* Ob = O + (size_t)(b * S_ + q0) * D_MODEL + h * D_KH;
    #pragma unroll
    for (int i = 0; i < 4; i++)
        #pragma unroll
        for (int j = 0; j < 4; j++)
            Ob[(size_t)(ty * 4 + i) * D_MODEL + tx * 4 + j] = acc[i][j];
}

// =====================================================================
// Residual + LayerNorm. grid: (M_TOT), 256 threads.
// out[m,:] = LN(resid[m,:] + P[m,:]) * gamma + beta
// =====================================================================
__global__ void ln_kernel(const float* __restrict__ resid,
                          const float* __restrict__ P,
                          const float* __restrict__ gamma,
                          const float* __restrict__ beta,
                          float* __restrict__ out)
{
    const int m = blockIdx.x;
    const int tid = threadIdx.x;
    __shared__ float xs[D_MODEL];
    __shared__ float red[256];

    float local = 0.f;
    for (int i = tid; i < D_MODEL; i += 256) {
        float x = resid[(size_t)m * D_MODEL + i] + P[(size_t)m * D_MODEL + i];
        xs[i] = x;
        local += x;
    }
    red[tid] = local; __syncthreads();
    for (int s = 128; s > 0; s >>= 1) {
        if (tid < s) red[tid] += red[tid + s];
        __syncthreads();
    }
    const float mu = red[0] * (1.0f / D_MODEL);
    __syncthreads();

    local = 0.f;
    for (int i = tid; i < D_MODEL; i += 256) {
        float d = xs[i] - mu;
        local += d * d;
    }
    red[tid] = local; __syncthreads();
    for (int s = 128; s > 0; s >>= 1) {
        if (tid < s) red[tid] += red[tid + s];
        __syncthreads();
    }
    const float rstd = rsqrtf(red[0] * (1.0f / D_MODEL) + LN_EPS);

    for (int i = tid; i < D_MODEL; i += 256)
        out[(size_t)m * D_MODEL + i] = (xs[i] - mu) * rstd * gamma[i] + beta[i];
}

// =====================================================================
extern "C" void kernel_launch(void* const* d_in, const int* in_sizes, int n_in,
                              void* d_out, int out_size)
{
    const float* q    = (const float*)d_in[0];
    const float* k    = (const float*)d_in[1];
    const float* v    = (const float*)d_in[2];
    // d_in[3] = mask (int32) — causal tril; applied analytically
    const float* Wq   = (const float*)d_in[4];
    const float* bq   = (const float*)d_in[5];
    const float* Wk   = (const float*)d_in[6];
    const float* bk   = (const float*)d_in[7];
    const float* Wv   = (const float*)d_in[8];
    const float* bv   = (const float*)d_in[9];
    const float* Wo   = (const float*)d_in[10];
    const float* bo   = (const float*)d_in[11];
    const float* gamma = (const float*)d_in[12];
    const float* beta  = (const float*)d_in[13];

    float* out  = (float*)d_out;
    float* attn = out + (size_t)M_TOT * D_MODEL;   // (out, attn) packed

    float *Qp, *Kp, *Vp, *Op, *Pp;
    cudaGetSymbolAddress((void**)&Qp, g_Q);
    cudaGetSymbolAddress((void**)&Kp, g_K);
    cudaGetSymbolAddress((void**)&Vp, g_V);
    cudaGetSymbolAddress((void**)&Op, g_O);
    cudaGetSymbolAddress((void**)&Pp, g_P);

    dim3 gProj(M_TOT / 64, D_MODEL / 64);
    gemm_nt_bias<<<gProj, 256>>>(q, Wq, bq, Qp);
    gemm_nt_bias<<<gProj, 256>>>(k, Wk, bk, Kp);
    gemm_nt_bias<<<gProj, 256>>>(v, Wv, bv, Vp);

    dim3 gScores(S_ / 64, S_ / 64, B_ * N_HEADS);
    scores_kernel<<<gScores, 256>>>(Qp, Kp, attn);

    dim3 gSoft(S_, B_ * N_HEADS);
    softmax_kernel<<<gSoft, 256>>>(attn);

    dim3 gPV(S_ / 64, B_ * N_HEADS);
    pv_kernel<<<gPV, 256>>>(attn, Vp, Op);

    gemm_nt_bias<<<gProj, 256>>>(Op, Wo, bo, Pp);

    ln_kernel<<<M_TOT, 256>>>(q, Pp, gamma, beta, out);
}

// round 2
// speedup vs baseline: 1.3860x; 1.3860x over previous
#include <cuda_runtime.h>
#include <math.h>

#define D_MODEL 768
#define N_HEADS 12
#define D_KH    64
#define B_      2
#define S_      2048
#define M_TOT   (B_ * S_)
#define LN_EPS  1e-5f

// ---------------- scratch (allocation-free: __device__ globals) ----------------
__device__ float g_Q[(size_t)M_TOT * D_MODEL];
__device__ float g_K[(size_t)M_TOT * D_MODEL];
__device__ float g_V[(size_t)M_TOT * D_MODEL];
__device__ float g_O[(size_t)M_TOT * D_MODEL];
__device__ float g_P[(size_t)M_TOT * D_MODEL];

// =====================================================================
// GEMM (NT) 128x128x16, 256 thr, 8x8 micro-tile, float4 everywhere.
// C[m,n] = sum_k A[m,k]*W[n,k] + bias[n].  A:[M,768], W:[768,768] row-major.
// grid: (M/128, 768/128)
// =====================================================================
__global__ void __launch_bounds__(256, 2)
gemm_nt_bias(const float* __restrict__ A,
             const float* __restrict__ W,
             const float* __restrict__ bias,
             float* __restrict__ C)
{
    const int m0 = blockIdx.x * 128;
    const int n0 = blockIdx.y * 128;
    __shared__ float As[16][132];   // transposed: As[k][m]
    __shared__ float Ws[16][132];   // transposed: Ws[k][n]
    float acc[8][8] = {};
    const int tid = threadIdx.x;
    const int tx = tid & 15, ty = tid >> 4;

    for (int k0 = 0; k0 < 768; k0 += 16) {
        #pragma unroll
        for (int i = 0; i < 2; i++) {
            int f = tid + i * 256;            // 512 float4 per tile
            int r = f >> 2, c4 = (f & 3) * 4;
            float4 av = *(const float4*)&A[(size_t)(m0 + r) * 768 + k0 + c4];
            As[c4 + 0][r] = av.x; As[c4 + 1][r] = av.y;
            As[c4 + 2][r] = av.z; As[c4 + 3][r] = av.w;
            float4 wv = *(const float4*)&W[(size_t)(n0 + r) * 768 + k0 + c4];
            Ws[c4 + 0][r] = wv.x; Ws[c4 + 1][r] = wv.y;
            Ws[c4 + 2][r] = wv.z; Ws[c4 + 3][r] = wv.w;
        }
        __syncthreads();
        #pragma unroll
        for (int kk = 0; kk < 16; kk++) {
            float a[8], b[8];
            *(float4*)&a[0] = *(const float4*)&As[kk][ty * 8];
            *(float4*)&a[4] = *(const float4*)&As[kk][ty * 8 + 4];
            *(float4*)&b[0] = *(const float4*)&Ws[kk][tx * 8];
            *(float4*)&b[4] = *(const float4*)&Ws[kk][tx * 8 + 4];
            #pragma unroll
            for (int i = 0; i < 8; i++)
                #pragma unroll
                for (int j = 0; j < 8; j++)
                    acc[i][j] += a[i] * b[j];
        }
        __syncthreads();
    }
    float4 b0 = *(const float4*)&bias[n0 + tx * 8];
    float4 b1 = *(const float4*)&bias[n0 + tx * 8 + 4];
    #pragma unroll
    for (int i = 0; i < 8; i++) {
        float* cp = &C[(size_t)(m0 + ty * 8 + i) * 768 + n0 + tx * 8];
        float4 o0 = make_float4(acc[i][0] + b0.x, acc[i][1] + b0.y,
                                acc[i][2] + b0.z, acc[i][3] + b0.w);
        float4 o1 = make_float4(acc[i][4] + b1.x, acc[i][5] + b1.y,
                                acc[i][6] + b1.z, acc[i][7] + b1.w);
        *(float4*)cp = o0;
        *(float4*)(cp + 4) = o1;
    }
}

// =====================================================================
// Scores: attn_raw[bh,q,k] = 0.125 * Q.K  for kt<=qt tiles; zero-fill kt>qt.
// 128x128 tile, K=64.  grid: (S/128, S/128, B*H)
// =====================================================================
__global__ void __launch_bounds__(256, 2)
scores_kernel(const float* __restrict__ Q,
              const float* __restrict__ Kp,
              float* __restrict__ attn)
{
    const int qt = blockIdx.x;
    const int kt = blockIdx.y;
    const int bh = blockIdx.z;
    const int q0 = qt * 128, k0 = kt * 128;
    const int tid = threadIdx.x;

    if (kt > qt) {   // fully masked tile -> zeros (softmax never touches it)
        float4 z = make_float4(0.f, 0.f, 0.f, 0.f);
        float4* o4 = (float4*)(attn + ((size_t)bh * S_ + q0) * S_ + k0);
        #pragma unroll
        for (int i = 0; i < 16; i++) {
            int f = tid + i * 256;             // 4096 float4 in tile
            int r = f >> 5, c = f & 31;
            o4[(size_t)r * (S_ / 4) + c] = z;
        }
        return;
    }

    const int b = bh / N_HEADS, h = bh % N_HEADS;
    const float* Qb = Q  + (size_t)(b * S_) * D_MODEL + h * D_KH;
    const float* Kb = Kp + (size_t)(b * S_) * D_MODEL + h * D_KH;

    __shared__ float Qs[16][132];
    __shared__ float Ks[16][132];
    float acc[8][8] = {};
    const int tx = tid & 15, ty = tid >> 4;

    for (int kk0 = 0; kk0 < D_KH; kk0 += 16) {
        #pragma unroll
        for (int i = 0; i < 2; i++) {
            int f = tid + i * 256;
            int r = f >> 2, c4 = (f & 3) * 4;
            float4 qv = *(const float4*)&Qb[(size_t)(q0 + r) * D_MODEL + kk0 + c4];
            Qs[c4 + 0][r] = qv.x; Qs[c4 + 1][r] = qv.y;
            Qs[c4 + 2][r] = qv.z; Qs[c4 + 3][r] = qv.w;
            float4 kv = *(const float4*)&Kb[(size_t)(k0 + r) * D_MODEL + kk0 + c4];
            Ks[c4 + 0][r] = kv.x; Ks[c4 + 1][r] = kv.y;
            Ks[c4 + 2][r] = kv.z; Ks[c4 + 3][r] = kv.w;
        }
        __syncthreads();
        #pragma unroll
        for (int kk = 0; kk < 16; kk++) {
            float a[8], b2[8];
            *(float4*)&a[0]  = *(const float4*)&Qs[kk][ty * 8];
            *(float4*)&a[4]  = *(const float4*)&Qs[kk][ty * 8 + 4];
            *(float4*)&b2[0] = *(const float4*)&Ks[kk][tx * 8];
            *(float4*)&b2[4] = *(const float4*)&Ks[kk][tx * 8 + 4];
            #pragma unroll
            for (int i = 0; i < 8; i++)
                #pragma unroll
                for (int j = 0; j < 8; j++)
                    acc[i][j] += a[i] * b2[j];
        }
        __syncthreads();
    }
    #pragma unroll
    for (int i = 0; i < 8; i++) {
        float* op = attn + ((size_t)bh * S_ + q0 + ty * 8 + i) * S_ + k0 + tx * 8;
        float4 o0 = make_float4(acc[i][0] * 0.125f, acc[i][1] * 0.125f,
                                acc[i][2] * 0.125f, acc[i][3] * 0.125f);
        float4 o1 = make_float4(acc[i][4] * 0.125f, acc[i][5] * 0.125f,
                                acc[i][6] * 0.125f, acc[i][7] * 0.125f);
        *(float4*)op = o0;
        *(float4*)(op + 4) = o1;
    }
}

// =====================================================================
// Row softmax over cols [0, (qt+1)*128) only; causal mask inside.
// grid: (S, B*H), 256 threads, float4.
// =====================================================================
__global__ void softmax_kernel(float* __restrict__ attn)
{
    const int q  = blockIdx.x;
    const int bh = blockIdx.y;
    const int n4 = ((q >> 7) + 1) * 32;    // float4 count to process (<=512)
    float4* row4 = (float4*)(attn + ((size_t)bh * S_ + q) * S_);
    const int tid = threadIdx.x;
    const int lane = tid & 31, wid = tid >> 5;
    __shared__ float red[8];

    float4 v[2];
    int cnt = 0;
    float m = -INFINITY;
    for (int i = tid; i < n4; i += 256) {
        float4 t = row4[i];
        int c = i * 4;
        t.x = (c + 0 <= q) ? t.x : -INFINITY;
        t.y = (c + 1 <= q) ? t.y : -INFINITY;
        t.z = (c + 2 <= q) ? t.z : -INFINITY;
        t.w = (c + 3 <= q) ? t.w : -INFINITY;
        m = fmaxf(m, fmaxf(fmaxf(t.x, t.y), fmaxf(t.z, t.w)));
        v[cnt++] = t;
    }
    #pragma unroll
    for (int s = 16; s > 0; s >>= 1)
        m = fmaxf(m, __shfl_xor_sync(0xffffffff, m, s));
    if (lane == 0) red[wid] = m;
    __syncthreads();
    m = fmaxf(fmaxf(fmaxf(red[0], red[1]), fmaxf(red[2], red[3])),
              fmaxf(fmaxf(red[4], red[5]), fmaxf(red[6], red[7])));
    __syncthreads();

    float sum = 0.f;
    for (int j = 0; j < cnt; j++) {
        float4 t = v[j];
        t.x = __expf(t.x - m); t.y = __expf(t.y - m);
        t.z = __expf(t.z - m); t.w = __expf(t.w - m);
        sum += t.x + t.y + t.z + t.w;
        v[j] = t;
    }
    #pragma unroll
    for (int s = 16; s > 0; s >>= 1)
        sum += __shfl_xor_sync(0xffffffff, sum, s);
    if (lane == 0) red[wid] = sum;
    __syncthreads();
    sum = red[0] + red[1] + red[2] + red[3] + red[4] + red[5] + red[6] + red[7];
    const float inv = 1.0f / sum;

    for (int j = 0; j < cnt; j++) {
        float4 t = v[j];
        t.x *= inv; t.y *= inv; t.z *= inv; t.w *= inv;
        row4[tid + j * 256] = t;
    }
}

// =====================================================================
// PV: O[q,:64] = attn[q,0:kmax] @ V[:,h*64..]. 128x64 tile, 128 thr, 8x8.
// Heavy q-tiles scheduled first (reversed qt).  grid: (S/128, B*H)
// =====================================================================
__global__ void __launch_bounds__(128, 4)
pv_kernel(const float* __restrict__ attn,
          const float* __restrict__ V,
          float* __restrict__ O)
{
    const int qt = gridDim.x - 1 - blockIdx.x;   // heavy tiles first
    const int bh = blockIdx.y;
    const int b = bh / N_HEADS, h = bh % N_HEADS;
    const int q0 = qt * 128;

    const float* Arow = attn + ((size_t)bh * S_ + q0) * S_;
    const float* Vb   = V + (size_t)(b * S_) * D_MODEL + h * D_KH;

    __shared__ float As[16][132];   // transposed attn tile
    __shared__ float Bs[16][68];    // V tile, row-major
    float acc[8][8] = {};
    const int tid = threadIdx.x;
    const int tx = tid & 7, ty = tid >> 3;     // 8 x 16
    const int kmax = q0 + 128;

    for (int k0 = 0; k0 < kmax; k0 += 16) {
        #pragma unroll
        for (int i = 0; i < 4; i++) {          // 512 float4 of attn
            int f = tid + i * 128;
            int r = f >> 2, c4 = (f & 3) * 4;
            float4 av = *(const float4*)&Arow[(size_t)r * S_ + k0 + c4];
            As[c4 + 0][r] = av.x; As[c4 + 1][r] = av.y;
            As[c4 + 2][r] = av.z; As[c4 + 3][r] = av.w;
        }
        #pragma unroll
        for (int i = 0; i < 2; i++) {          // 256 float4 of V
            int f = tid + i * 128;
            int r = f >> 4, c4 = (f & 15) * 4;
            float4 vv = *(const float4*)&Vb[(size_t)(k0 + r) * D_MODEL + c4];
            *(float4*)&Bs[r][c4] = vv;
        }
        __syncthreads();
        #pragma unroll
        for (int kk = 0; kk < 16; kk++) {
            float a[8], b2[8];
            *(float4*)&a[0]  = *(const float4*)&As[kk][ty * 8];
            *(float4*)&a[4]  = *(const float4*)&As[kk][ty * 8 + 4];
            *(float4*)&b2[0] = *(const float4*)&Bs[kk][tx * 8];
            *(float4*)&b2[4] = *(const float4*)&Bs[kk][tx * 8 + 4];
            #pragma unroll
            for (int i = 0; i < 8; i++)
                #pragma unroll
                for (int j = 0; j < 8; j++)
                    acc[i][j] += a[i] * b2[j];
        }
        __syncthreads();
    }
    float* Ob = O + (size_t)(b * S_ + q0) * D_MODEL + h * D_KH;
    #pragma unroll
    for (int i = 0; i < 8; i++) {
        float* op = &Ob[(size_t)(ty * 8 + i) * D_MODEL + tx * 8];
        *(float4*)op       = make_float4(acc[i][0], acc[i][1], acc[i][2], acc[i][3]);
        *(float4*)(op + 4) = make_float4(acc[i][4], acc[i][5], acc[i][6], acc[i][7]);
    }
}

// =====================================================================
// Residual + LayerNorm, float4, 192 threads (one float4 per thread).
// =====================================================================
__global__ void ln_kernel(const float* __restrict__ resid,
                          const float* __restrict__ P,
                          const float* __restrict__ gamma,
                          const float* __restrict__ beta,
                          float* __restrict__ out)
{
    const int m = blockIdx.x;
    const int tid = threadIdx.x;          // 0..191
    const int lane = tid & 31, wid = tid >> 5;
    __shared__ float red[6];

    const float4* r4 = (const float4*)(resid + (size_t)m * D_MODEL);
    const float4* p4 = (const float4*)(P + (size_t)m * D_MODEL);
    float4 a = r4[tid], b = p4[tid];
    float4 x = make_float4(a.x + b.x, a.y + b.y, a.z + b.z, a.w + b.w);

    float s = x.x + x.y + x.z + x.w;
    #pragma unroll
    for (int sh = 16; sh > 0; sh >>= 1)
        s += __shfl_xor_sync(0xffffffff, s, sh);
    if (lane == 0) red[wid] = s;
    __syncthreads();
    s = red[0] + red[1] + red[2] + red[3] + red[4] + red[5];
    const float mu = s * (1.0f / D_MODEL);
    __syncthreads();

    float4 d = make_float4(x.x - mu, x.y - mu, x.z - mu, x.w - mu);
    float v = d.x * d.x + d.y * d.y + d.z * d.z + d.w * d.w;
    #pragma unroll
    for (int sh = 16; sh > 0; sh >>= 1)
        v += __shfl_xor_sync(0xffffffff, v, sh);
    if (lane == 0) red[wid] = v;
    __syncthreads();
    v = red[0] + red[1] + red[2] + red[3] + red[4] + red[5];
    const float rstd = rsqrtf(v * (1.0f / D_MODEL) + LN_EPS);

    float4 g = ((const float4*)gamma)[tid];
    float4 be = ((const float4*)beta)[tid];
    float4 o = make_float4(d.x * rstd * g.x + be.x,
                           d.y * rstd * g.y + be.y,
                           d.z * rstd * g.z + be.z,
                           d.w * rstd * g.w + be.w);
    ((float4*)(out + (size_t)m * D_MODEL))[tid] = o;
}

// =====================================================================
extern "C" void kernel_launch(void* const* d_in, const int* in_sizes, int n_in,
                              void* d_out, int out_size)
{
    const float* q     = (const float*)d_in[0];
    const float* k     = (const float*)d_in[1];
    const float* v     = (const float*)d_in[2];
    const float* Wq    = (const float*)d_in[4];
    const float* bq    = (const float*)d_in[5];
    const float* Wk    = (const float*)d_in[6];
    const float* bk    = (const float*)d_in[7];
    const float* Wv    = (const float*)d_in[8];
    const float* bv    = (const float*)d_in[9];
    const float* Wo    = (const float*)d_in[10];
    const float* bo    = (const float*)d_in[11];
    const float* gamma = (const float*)d_in[12];
    const float* beta  = (const float*)d_in[13];

    float* out  = (float*)d_out;
    float* attn = out + (size_t)M_TOT * D_MODEL;

    float *Qp, *Kp, *Vp, *Op, *Pp;
    cudaGetSymbolAddress((void**)&Qp, g_Q);
    cudaGetSymbolAddress((void**)&Kp, g_K);
    cudaGetSymbolAddress((void**)&Vp, g_V);
    cudaGetSymbolAddress((void**)&Op, g_O);
    cudaGetSymbolAddress((void**)&Pp, g_P);

    dim3 gProj(M_TOT / 128, D_MODEL / 128);
    gemm_nt_bias<<<gProj, 256>>>(q, Wq, bq, Qp);
    gemm_nt_bias<<<gProj, 256>>>(k, Wk, bk, Kp);
    gemm_nt_bias<<<gProj, 256>>>(v, Wv, bv, Vp);

    dim3 gScores(S_ / 128, S_ / 128, B_ * N_HEADS);
    scores_kernel<<<gScores, 256>>>(Qp, Kp, attn);

    dim3 gSoft(S_, B_ * N_HEADS);
    softmax_kernel<<<gSoft, 256>>>(attn);

    dim3 gPV(S_ / 128, B_ * N_HEADS);
    pv_kernel<<<gPV, 128>>>(attn, Vp, Op);

    gemm_nt_bias<<<gProj, 256>>>(Op, Wo, bo, Pp);

    ln_kernel<<<M_TOT, 192>>>(q, Pp, gamma, beta, out);
}

// round 4
// speedup vs baseline: 2.5527x; 1.8417x over previous
#include <cuda_runtime.h>
#include <cuda_bf16.h>
#include <math.h>
#include <stdint.h>

#define D_MODEL 768
#define N_HEADS 12
#define D_KH    64
#define B_      2
#define S_      2048
#define M_TOT   (B_ * S_)
#define LN_EPS  1e-5f

// ---------------- scratch (allocation-free: __device__ globals) ----------------
__device__ float g_Q[(size_t)M_TOT * D_MODEL];
__device__ float g_K[(size_t)M_TOT * D_MODEL];
__device__ float g_V[(size_t)M_TOT * D_MODEL];
__device__ float g_O[(size_t)M_TOT * D_MODEL];
__device__ float g_P[(size_t)M_TOT * D_MODEL];

// ======================= warp-MMA helpers =======================
__device__ __forceinline__ uint32_t smem_u32(const void* p) {
    uint32_t a;
    asm("{ .reg .u64 t; cvta.to.shared.u64 t, %1; cvt.u32.u64 %0, t; }"
        : "=r"(a) : "l"(p));
    return a;
}

__device__ __forceinline__ void ldm_x4(uint32_t* r, uint32_t addr) {
    asm volatile("ldmatrix.sync.aligned.m8n8.x4.shared.b16 {%0,%1,%2,%3}, [%4];"
                 : "=r"(r[0]), "=r"(r[1]), "=r"(r[2]), "=r"(r[3]) : "r"(addr));
}
__device__ __forceinline__ void ldm_x2(uint32_t* r, uint32_t addr) {
    asm volatile("ldmatrix.sync.aligned.m8n8.x2.shared.b16 {%0,%1}, [%2];"
                 : "=r"(r[0]), "=r"(r[1]) : "r"(addr));
}
__device__ __forceinline__ void ldm_x2_trans(uint32_t* r, uint32_t addr) {
    asm volatile("ldmatrix.sync.aligned.m8n8.x2.trans.shared.b16 {%0,%1}, [%2];"
                 : "=r"(r[0]), "=r"(r[1]) : "r"(addr));
}
// D += A * B  (m16n8k16, bf16 in, fp32 accum)
__device__ __forceinline__ void mma_bf16(float* c, const uint32_t* a, const uint32_t* b) {
    asm volatile(
        "mma.sync.aligned.m16n8k16.row.col.f32.bf16.bf16.f32 "
        "{%0,%1,%2,%3}, {%4,%5,%6,%7}, {%8,%9}, {%0,%1,%2,%3};"
        : "+f"(c[0]), "+f"(c[1]), "+f"(c[2]), "+f"(c[3])
        : "r"(a[0]), "r"(a[1]), "r"(a[2]), "r"(a[3]), "r"(b[0]), "r"(b[1]));
}

// split fp32 -> (hi,lo) bf16; pack 4 values to uint2 (4 halves = 8B)
__device__ __forceinline__ uint32_t pack2(__nv_bfloat16 a, __nv_bfloat16 b) {
    return ((uint32_t)__bfloat16_as_ushort(b) << 16) | (uint32_t)__bfloat16_as_ushort(a);
}
__device__ __forceinline__ void split4(float4 v, uint2& hi, uint2& lo) {
    __nv_bfloat16 h0 = __float2bfloat16(v.x), h1 = __float2bfloat16(v.y);
    __nv_bfloat16 h2 = __float2bfloat16(v.z), h3 = __float2bfloat16(v.w);
    hi = make_uint2(pack2(h0, h1), pack2(h2, h3));
    __nv_bfloat16 l0 = __float2bfloat16(v.x - __bfloat162float(h0));
    __nv_bfloat16 l1 = __float2bfloat16(v.y - __bfloat162float(h1));
    __nv_bfloat16 l2 = __float2bfloat16(v.z - __bfloat162float(h2));
    __nv_bfloat16 l3 = __float2bfloat16(v.w - __bfloat162float(h3));
    lo = make_uint2(pack2(l0, l1), pack2(l2, l3));
}

#define LDA 40   // padded row stride (halves) for 32-wide K-chunk tiles
#define LDV 72   // padded row stride (halves) for 64-wide V tiles

// =====================================================================
// GEMM (NT) + bias via mma.sync, split-bf16 (3 terms).
// C[m,n] = sum_k A[m,k]*W[n,k] + bias[n]. Tile 128x128, K-chunk 32.
// 256 thr = 8 warps, warp tile 64x32. grid (M/128, 768/128)
// =====================================================================
__global__ void __launch_bounds__(256, 2)
gemm_mma(const float* __restrict__ A, const float* __restrict__ W,
         const float* __restrict__ bias, float* __restrict__ C)
{
    __shared__ __align__(16) uint16_t Ah[128][LDA], Al[128][LDA];
    __shared__ __align__(16) uint16_t Bh[128][LDA], Bl[128][LDA];
    const int tid = threadIdx.x, wid = tid >> 5, lane = tid & 31;
    const int m0 = blockIdx.x * 128, n0 = blockIdx.y * 128;
    const int wm = (wid & 1) * 64, wn = (wid >> 1) * 32;
    const uint32_t aHb = smem_u32(Ah), aLb = smem_u32(Al);
    const uint32_t bHb = smem_u32(Bh), bLb = smem_u32(Bl);

    float acc[4][4][4] = {};

    for (int k0 = 0; k0 < 768; k0 += 32) {
        #pragma unroll
        for (int i = 0; i < 4; i++) {
            int f = tid + i * 256;
            int r = f >> 3, c4 = (f & 7) * 4;
            uint2 hi, lo;
            split4(*(const float4*)&A[(size_t)(m0 + r) * 768 + k0 + c4], hi, lo);
            *(uint2*)&Ah[r][c4] = hi; *(uint2*)&Al[r][c4] = lo;
            split4(*(const float4*)&W[(size_t)(n0 + r) * 768 + k0 + c4], hi, lo);
            *(uint2*)&Bh[r][c4] = hi; *(uint2*)&Bl[r][c4] = lo;
        }
        __syncthreads();
        #pragma unroll
        for (int ks = 0; ks < 2; ks++) {
            uint32_t ah[4][4], al[4][4];
            const int arow = wm + (lane & 7) + ((lane >> 3) & 1) * 8;
            const int acol = ks * 16 + (lane >> 4) * 8;
            #pragma unroll
            for (int mt = 0; mt < 4; mt++) {
                uint32_t off = ((arow + mt * 16) * LDA + acol) * 2;
                ldm_x4(ah[mt], aHb + off);
                ldm_x4(al[mt], aLb + off);
            }
            const int brow = wn + (lane & 7);
            const int bcol = ks * 16 + ((lane >> 3) & 1) * 8;
            #pragma unroll
            for (int nt = 0; nt < 4; nt++) {
                uint32_t off = ((brow + nt * 8) * LDA + bcol) * 2;
                uint32_t bh[2], bl[2];
                ldm_x2(bh, bHb + off);
                ldm_x2(bl, bLb + off);
                #pragma unroll
                for (int mt = 0; mt < 4; mt++) {
                    mma_bf16(acc[mt][nt], ah[mt], bh);
                    mma_bf16(acc[mt][nt], ah[mt], bl);
                    mma_bf16(acc[mt][nt], al[mt], bh);
                }
            }
        }
        __syncthreads();
    }
    #pragma unroll
    for (int mt = 0; mt < 4; mt++) {
        const int m = m0 + wm + mt * 16 + (lane >> 2);
        #pragma unroll
        for (int nt = 0; nt < 4; nt++) {
            const int n = n0 + wn + nt * 8 + (lane & 3) * 2;
            float2 bv = *(const float2*)&bias[n];
            *(float2*)&C[(size_t)m * 768 + n] =
                make_float2(acc[mt][nt][0] + bv.x, acc[mt][nt][1] + bv.y);
            *(float2*)&C[(size_t)(m + 8) * 768 + n] =
                make_float2(acc[mt][nt][2] + bv.x, acc[mt][nt][3] + bv.y);
        }
    }
}

// =====================================================================
// Scores via mma.sync: attn[bh,q,k] = 0.125*(Q.K) for kt<=qt; zeros else.
// Tile 128x128, K=64 (2 chunks of 32). grid (S/128, S/128, B*H)
// =====================================================================
__global__ void __launch_bounds__(256, 2)
scores_mma(const float* __restrict__ Q, const float* __restrict__ Kp,
           float* __restrict__ attn)
{
    const int qt = blockIdx.x, kt = blockIdx.y, bh = blockIdx.z;
    const int q0 = qt * 128, k0 = kt * 128;
    const int tid = threadIdx.x;

    if (kt > qt) {   // fully masked -> zero-fill (softmax only reads <= q)
        float4 z = make_float4(0.f, 0.f, 0.f, 0.f);
        float4* o4 = (float4*)(attn + ((size_t)bh * S_ + q0) * S_ + k0);
        #pragma unroll
        for (int i = 0; i < 16; i++) {
            int f = tid + i * 256;
            int r = f >> 5, c = f & 31;
            o4[(size_t)r * (S_ / 4) + c] = z;
        }
        return;
    }

    __shared__ __align__(16) uint16_t Ah[128][LDA], Al[128][LDA];
    __shared__ __align__(16) uint16_t Bh[128][LDA], Bl[128][LDA];
    const int wid = tid >> 5, lane = tid & 31;
    const int b = bh / N_HEADS, h = bh % N_HEADS;
    const float* Qb = Q  + (size_t)(b * S_) * D_MODEL + h * D_KH;
    const float* Kb = Kp + (size_t)(b * S_) * D_MODEL + h * D_KH;
    const int wm = (wid & 1) * 64, wn = (wid >> 1) * 32;
    const uint32_t aHb = smem_u32(Ah), aLb = smem_u32(Al);
    const uint32_t bHb = smem_u32(Bh), bLb = smem_u32(Bl);

    float acc[4][4][4] = {};

    #pragma unroll
    for (int c = 0; c < 2; c++) {
        const int d0 = c * 32;
        #pragma unroll
        for (int i = 0; i < 4; i++) {
            int f = tid + i * 256;
            int r = f >> 3, c4 = (f & 7) * 4;
            uint2 hi, lo;
            split4(*(const float4*)&Qb[(size_t)(q0 + r) * D_MODEL + d0 + c4], hi, lo);
            *(uint2*)&Ah[r][c4] = hi; *(uint2*)&Al[r][c4] = lo;
            split4(*(const float4*)&Kb[(size_t)(k0 + r) * D_MODEL + d0 + c4], hi, lo);
            *(uint2*)&Bh[r][c4] = hi; *(uint2*)&Bl[r][c4] = lo;
        }
        __syncthreads();
        #pragma unroll
        for (int ks = 0; ks < 2; ks++) {
            uint32_t ah[4][4], al[4][4];
            const int arow = wm + (lane & 7) + ((lane >> 3) & 1) * 8;
            const int acol = ks * 16 + (lane >> 4) * 8;
            #pragma unroll
            for (int mt = 0; mt < 4; mt++) {
                uint32_t off = ((arow + mt * 16) * LDA + acol) * 2;
                ldm_x4(ah[mt], aHb + off);
                ldm_x4(al[mt], aLb + off);
            }
            const int brow = wn + (lane & 7);
            const int bcol = ks * 16 + ((lane >> 3) & 1) * 8;
            #pragma unroll
            for (int nt = 0; nt < 4; nt++) {
                uint32_t off = ((brow + nt * 8) * LDA + bcol) * 2;
                uint32_t bh2[2], bl2[2];
                ldm_x2(bh2, bHb + off);
                ldm_x2(bl2, bLb + off);
                #pragma unroll
                for (int mt = 0; mt < 4; mt++) {
                    mma_bf16(acc[mt][nt], ah[mt], bh2);
                    mma_bf16(acc[mt][nt], ah[mt], bl2);
                    mma_bf16(acc[mt][nt], al[mt], bh2);
                }
            }
        }
        __syncthreads();
    }
    #pragma unroll
    for (int mt = 0; mt < 4; mt++) {
        const int qrow = q0 + wm + mt * 16 + (lane >> 2);
        #pragma unroll
        for (int nt = 0; nt < 4; nt++) {
            const int kcol = k0 + wn + nt * 8 + (lane & 3) * 2;
            float* op0 = attn + ((size_t)bh * S_ + qrow) * S_ + kcol;
            float* op1 = attn + ((size_t)bh * S_ + qrow + 8) * S_ + kcol;
            *(float2*)op0 = make_float2(acc[mt][nt][0] * 0.125f, acc[mt][nt][1] * 0.125f);
            *(float2*)op1 = make_float2(acc[mt][nt][2] * 0.125f, acc[mt][nt][3] * 0.125f);
        }
    }
}

// =====================================================================
// Row softmax over cols [0, (qt+1)*128); causal mask inside.
// =====================================================================
__global__ void softmax_kernel(float* __restrict__ attn)
{
    const int q  = blockIdx.x;
    const int bh = blockIdx.y;
    const int n4 = ((q >> 7) + 1) * 32;
    float4* row4 = (float4*)(attn + ((size_t)bh * S_ + q) * S_);
    const int tid = threadIdx.x;
    const int lane = tid & 31, wid = tid >> 5;
    __shared__ float red[8];

    float4 v[2];
    int cnt = 0;
    float m = -INFINITY;
    for (int i = tid; i < n4; i += 256) {
        float4 t = row4[i];
        int c = i * 4;
        t.x = (c + 0 <= q) ? t.x : -INFINITY;
        t.y = (c + 1 <= q) ? t.y : -INFINITY;
        t.z = (c + 2 <= q) ? t.z : -INFINITY;
        t.w = (c + 3 <= q) ? t.w : -INFINITY;
        m = fmaxf(m, fmaxf(fmaxf(t.x, t.y), fmaxf(t.z, t.w)));
        v[cnt++] = t;
    }
    #pragma unroll
    for (int s = 16; s > 0; s >>= 1)
        m = fmaxf(m, __shfl_xor_sync(0xffffffff, m, s));
    if (lane == 0) red[wid] = m;
    __syncthreads();
    m = fmaxf(fmaxf(fmaxf(red[0], red[1]), fmaxf(red[2], red[3])),
              fmaxf(fmaxf(red[4], red[5]), fmaxf(red[6], red[7])));
    __syncthreads();

    float sum = 0.f;
    for (int j = 0; j < cnt; j++) {
        float4 t = v[j];
        t.x = __expf(t.x - m); t.y = __expf(t.y - m);
        t.z = __expf(t.z - m); t.w = __expf(t.w - m);
        sum += t.x + t.y + t.z + t.w;
        v[j] = t;
    }
    #pragma unroll
    for (int s = 16; s > 0; s >>= 1)
        sum += __shfl_xor_sync(0xffffffff, sum, s);
    if (lane == 0) red[wid] = sum;
    __syncthreads();
    sum = red[0] + red[1] + red[2] + red[3] + red[4] + red[5] + red[6] + red[7];
    const float inv = 1.0f / sum;

    for (int j = 0; j < cnt; j++) {
        float4 t = v[j];
        t.x *= inv; t.y *= inv; t.z *= inv; t.w *= inv;
        row4[tid + j * 256] = t;
    }
}

// =====================================================================
// PV via mma.sync: O[q,d] = sum_k P[q,k]*V[k,d]. Tile 128(q)x64(d),
// K-chunks of 32 up to (qt+1)*128. V loaded [k][d], ldmatrix .trans.
// 256 thr, warp tile 32x32 (4m x 2n warps). grid (S/128, B*H)
// =====================================================================
__global__ void __launch_bounds__(256, 2)
pv_mma(const float* __restrict__ attn, const float* __restrict__ V,
       float* __restrict__ O)
{
    __shared__ __align__(16) uint16_t Ph[128][LDA], Pl[128][LDA];
    __shared__ __align__(16) uint16_t Vh[32][LDV], Vl[32][LDV];
    const int tid = threadIdx.x, wid = tid >> 5, lane = tid & 31;
    const int qt = gridDim.x - 1 - blockIdx.x;   // heavy tiles first
    const int bh = blockIdx.y;
    const int b = bh / N_HEADS, h = bh % N_HEADS;
    const int q0 = qt * 128;
    const int wm = (wid & 3) * 32, wn = (wid >> 2) * 32;
    const uint32_t pHb = smem_u32(Ph), pLb = smem_u32(Pl);
    const uint32_t vHb = smem_u32(Vh), vLb = smem_u32(Vl);

    const float* Arow = attn + ((size_t)bh * S_ + q0) * S_;
    const float* Vb   = V + (size_t)(b * S_) * D_MODEL + h * D_KH;

    float acc[2][4][4] = {};
    const int n_chunks = 4 * (qt + 1);

    for (int c = 0; c < n_chunks; c++) {
        const int k0 = c * 32;
        #pragma unroll
        for (int i = 0; i < 4; i++) {          // P chunk 128x32
            int f = tid + i * 256;
            int r = f >> 3, c4 = (f & 7) * 4;
            uint2 hi, lo;
            split4(*(const float4*)&Arow[(size_t)r * S_ + k0 + c4], hi, lo);
            *(uint2*)&Ph[r][c4] = hi; *(uint2*)&Pl[r][c4] = lo;
        }
        #pragma unroll
        for (int i = 0; i < 2; i++) {          // V chunk 32x64
            int f = tid + i * 256;
            int r = f >> 4, c4 = (f & 15) * 4;
            uint2 hi, lo;
            split4(*(const float4*)&Vb[(size_t)(k0 + r) * D_MODEL + c4], hi, lo);
            *(uint2*)&Vh[r][c4] = hi; *(uint2*)&Vl[r][c4] = lo;
        }
        __syncthreads();
        #pragma unroll
        for (int ks = 0; ks < 2; ks++) {
            uint32_t ph[2][4], pl[2][4];
            const int arow = wm + (lane & 7) + ((lane >> 3) & 1) * 8;
            const int acol = ks * 16 + (lane >> 4) * 8;
            #pragma unroll
            for (int mt = 0; mt < 2; mt++) {
                uint32_t off = ((arow + mt * 16) * LDA + acol) * 2;
                ldm_x4(ph[mt], pHb + off);
                ldm_x4(pl[mt], pLb + off);
            }
            const int krow = ks * 16 + ((lane >> 3) & 1) * 8 + (lane & 7);
            #pragma unroll
            for (int nt = 0; nt < 4; nt++) {
                uint32_t off = ((uint32_t)krow * LDV + wn + nt * 8) * 2;
                uint32_t vh2[2], vl2[2];
                ldm_x2_trans(vh2, vHb + off);
                ldm_x2_trans(vl2, vLb + off);
                #pragma unroll
                for (int mt = 0; mt < 2; mt++) {
                    mma_bf16(acc[mt][nt], ph[mt], vh2);
                    mma_bf16(acc[mt][nt], ph[mt], vl2);
                    mma_bf16(acc[mt][nt], pl[mt], vh2);
                }
            }
        }
        __syncthreads();
    }
    #pragma unroll
    for (int mt = 0; mt < 2; mt++) {
        const int qrow = q0 + wm + mt * 16 + (lane >> 2);
        float* Ob0 = O + (size_t)(b * S_ + qrow) * D_MODEL + h * D_KH;
        float* Ob1 = O + (size_t)(b * S_ + qrow + 8) * D_MODEL + h * D_KH;
        #pragma unroll
        for (int nt = 0; nt < 4; nt++) {
            const int n = wn + nt * 8 + (lane & 3) * 2;
            *(float2*)&Ob0[n] = make_float2(acc[mt][nt][0], acc[mt][nt][1]);
            *(float2*)&Ob1[n] = make_float2(acc[mt][nt][2], acc[mt][nt][3]);
        }
    }
}

// =====================================================================
// Residual + LayerNorm, float4, 192 threads.
// =====================================================================
__global__ void ln_kernel(const float* __restrict__ resid,
                          const float* __restrict__ P,
                          const float* __restrict__ gamma,
                          const float* __restrict__ beta,
                          float* __restrict__ out)
{
    const int m = blockIdx.x;
    const int tid = threadIdx.x;
    const int lane = tid & 31, wid = tid >> 5;
    __shared__ float red[6];

    const float4* r4 = (const float4*)(resid + (size_t)m * D_MODEL);
    const float4* p4 = (const float4*)(P + (size_t)m * D_MODEL);
    float4 a = r4[tid], b = p4[tid];
    float4 x = make_float4(a.x + b.x, a.y + b.y, a.z + b.z, a.w + b.w);

    float s = x.x + x.y + x.z + x.w;
    #pragma unroll
    for (int sh = 16; sh > 0; sh >>= 1)
        s += __shfl_xor_sync(0xffffffff, s, sh);
    if (lane == 0) red[wid] = s;
    __syncthreads();
    s = red[0] + red[1] + red[2] + red[3] + red[4] + red[5];
    const float mu = s * (1.0f / D_MODEL);
    __syncthreads();

    float4 d = make_float4(x.x - mu, x.y - mu, x.z - mu, x.w - mu);
    float v = d.x * d.x + d.y * d.y + d.z * d.z + d.w * d.w;
    #pragma unroll
    for (int sh = 16; sh > 0; sh >>= 1)
        v += __shfl_xor_sync(0xffffffff, v, sh);
    if (lane == 0) red[wid] = v;
    __syncthreads();
    v = red[0] + red[1] + red[2] + red[3] + red[4] + red[5];
    const float rstd = rsqrtf(v * (1.0f / D_MODEL) + LN_EPS);

    float4 g = ((const float4*)gamma)[tid];
    float4 be = ((const float4*)beta)[tid];
    float4 o = make_float4(d.x * rstd * g.x + be.x,
                           d.y * rstd * g.y + be.y,
                           d.z * rstd * g.z + be.z,
                           d.w * rstd * g.w + be.w);
    ((float4*)(out + (size_t)m * D_MODEL))[tid] = o;
}

// =====================================================================
extern "C" void kernel_launch(void* const* d_in, const int* in_sizes, int n_in,
                              void* d_out, int out_size)
{
    const float* q     = (const float*)d_in[0];
    const float* k     = (const float*)d_in[1];
    const float* v     = (const float*)d_in[2];
    const float* Wq    = (const float*)d_in[4];
    const float* bq    = (const float*)d_in[5];
    const float* Wk    = (const float*)d_in[6];
    const float* bk    = (const float*)d_in[7];
    const float* Wv    = (const float*)d_in[8];
    const float* bv    = (const float*)d_in[9];
    const float* Wo    = (const float*)d_in[10];
    const float* bo    = (const float*)d_in[11];
    const float* gamma = (const float*)d_in[12];
    const float* beta  = (const float*)d_in[13];

    float* out  = (float*)d_out;
    float* attn = out + (size_t)M_TOT * D_MODEL;

    float *Qp, *Kp, *Vp, *Op, *Pp;
    cudaGetSymbolAddress((void**)&Qp, g_Q);
    cudaGetSymbolAddress((void**)&Kp, g_K);
    cudaGetSymbolAddress((void**)&Vp, g_V);
    cudaGetSymbolAddress((void**)&Op, g_O);
    cudaGetSymbolAddress((void**)&Pp, g_P);

    dim3 gProj(M_TOT / 128, D_MODEL / 128);
    gemm_mma<<<gProj, 256>>>(q, Wq, bq, Qp);
    gemm_mma<<<gProj, 256>>>(k, Wk, bk, Kp);
    gemm_mma<<<gProj, 256>>>(v, Wv, bv, Vp);

    dim3 gScores(S_ / 128, S_ / 128, B_ * N_HEADS);
    scores_mma<<<gScores, 256>>>(Qp, Kp, attn);

    dim3 gSoft(S_, B_ * N_HEADS);
    softmax_kernel<<<gSoft, 256>>>(attn);

    dim3 gPV(S_ / 128, B_ * N_HEADS);
    pv_mma<<<gPV, 256>>>(attn, Vp, Op);

    gemm_mma<<<gProj, 256>>>(Op, Wo, bo, Pp);

    ln_kernel<<<M_TOT, 192>>>(q, Pp, gamma, beta, out);
}

// round 5
// speedup vs baseline: 2.6362x; 1.0327x over previous
#include <cuda_runtime.h>
#include <cuda_bf16.h>
#include <math.h>
#include <stdint.h>

#define D_MODEL 768
#define N_HEADS 12
#define D_KH    64
#define B_      2
#define S_      2048
#define M_TOT   (B_ * S_)
#define LN_EPS  1e-5f
#define NELEM   ((size_t)M_TOT * D_MODEL)   // 3145728
#define WELEM   ((size_t)D_MODEL * D_MODEL) // 589824

// ---------------- scratch (allocation-free: __device__ globals) ----------------
__device__ uint16_t g_inqh[NELEM], g_inql[NELEM];
__device__ uint16_t g_inkh[NELEM], g_inkl[NELEM];
__device__ uint16_t g_invh[NELEM], g_invl[NELEM];
__device__ uint16_t g_wqh[WELEM], g_wql[WELEM];
__device__ uint16_t g_wkh[WELEM], g_wkl[WELEM];
__device__ uint16_t g_wvh[WELEM], g_wvl[WELEM];
__device__ uint16_t g_woh[WELEM], g_wol[WELEM];
__device__ uint16_t g_Qh[NELEM], g_Ql[NELEM];
__device__ uint16_t g_Kh[NELEM], g_Kl[NELEM];
__device__ uint16_t g_Vh[NELEM], g_Vl[NELEM];
__device__ uint16_t g_Oh[NELEM], g_Ol[NELEM];
__device__ float    g_P[NELEM];

// ======================= helpers =======================
__device__ __forceinline__ uint32_t smem_u32(const void* p) {
    uint32_t a;
    asm("{ .reg .u64 t; cvta.to.shared.u64 t, %1; cvt.u32.u64 %0, t; }"
        : "=r"(a) : "l"(p));
    return a;
}
__device__ __forceinline__ void ldm_x4(uint32_t* r, uint32_t addr) {
    asm volatile("ldmatrix.sync.aligned.m8n8.x4.shared.b16 {%0,%1,%2,%3}, [%4];"
                 : "=r"(r[0]), "=r"(r[1]), "=r"(r[2]), "=r"(r[3]) : "r"(addr));
}
__device__ __forceinline__ void ldm_x2(uint32_t* r, uint32_t addr) {
    asm volatile("ldmatrix.sync.aligned.m8n8.x2.shared.b16 {%0,%1}, [%2];"
                 : "=r"(r[0]), "=r"(r[1]) : "r"(addr));
}
__device__ __forceinline__ void ldm_x2_trans(uint32_t* r, uint32_t addr) {
    asm volatile("ldmatrix.sync.aligned.m8n8.x2.trans.shared.b16 {%0,%1}, [%2];"
                 : "=r"(r[0]), "=r"(r[1]) : "r"(addr));
}
__device__ __forceinline__ void mma_bf16(float* c, const uint32_t* a, const uint32_t* b) {
    asm volatile(
        "mma.sync.aligned.m16n8k16.row.col.f32.bf16.bf16.f32 "
        "{%0,%1,%2,%3}, {%4,%5,%6,%7}, {%8,%9}, {%0,%1,%2,%3};"
        : "+f"(c[0]), "+f"(c[1]), "+f"(c[2]), "+f"(c[3])
        : "r"(a[0]), "r"(a[1]), "r"(a[2]), "r"(a[3]), "r"(b[0]), "r"(b[1]));
}
__device__ __forceinline__ void cp16(uint32_t s, const void* g) {
    asm volatile("cp.async.cg.shared.global [%0], [%1], 16;" :: "r"(s), "l"(g));
}
#define CP_COMMIT() asm volatile("cp.async.commit_group;")
#define CP_WAIT0()  asm volatile("cp.async.wait_group 0;")
#define CP_WAIT1()  asm volatile("cp.async.wait_group 1;")

__device__ __forceinline__ uint32_t pack2(__nv_bfloat16 a, __nv_bfloat16 b) {
    return ((uint32_t)__bfloat16_as_ushort(b) << 16) | (uint32_t)__bfloat16_as_ushort(a);
}
__device__ __forceinline__ void split4(float4 v, uint2& hi, uint2& lo) {
    __nv_bfloat16 h0 = __float2bfloat16(v.x), h1 = __float2bfloat16(v.y);
    __nv_bfloat16 h2 = __float2bfloat16(v.z), h3 = __float2bfloat16(v.w);
    hi = make_uint2(pack2(h0, h1), pack2(h2, h3));
    __nv_bfloat16 l0 = __float2bfloat16(v.x - __bfloat162float(h0));
    __nv_bfloat16 l1 = __float2bfloat16(v.y - __bfloat162float(h1));
    __nv_bfloat16 l2 = __float2bfloat16(v.z - __bfloat162float(h2));
    __nv_bfloat16 l3 = __float2bfloat16(v.w - __bfloat162float(h3));
    lo = make_uint2(pack2(l0, l1), pack2(l2, l3));
}
__device__ __forceinline__ void split2(float x, float y, uint32_t& hi, uint32_t& lo) {
    __nv_bfloat16 h0 = __float2bfloat16(x), h1 = __float2bfloat16(y);
    hi = pack2(h0, h1);
    lo = pack2(__float2bfloat16(x - __bfloat162float(h0)),
               __float2bfloat16(y - __bfloat162float(h1)));
}

// ======================= split convert kernel =======================
__global__ void split_kernel(const float4* __restrict__ in,
                             uint2* __restrict__ hi, uint2* __restrict__ lo)
{
    int i = blockIdx.x * 256 + threadIdx.x;
    uint2 h, l;
    split4(in[i], h, l);
    hi[i] = h; lo[i] = l;
}

#define LDA 40   // padded row stride (halves), 32-wide chunks
#define LDV 72   // padded row stride (halves), 64-wide tiles

// =====================================================================
// Pipelined split-bf16 GEMM (NT): C = A @ W^T + bias
// Pre-split operands, cp.async 2-stage pipeline, K-chunk 32 (24 chunks).
// Tile 128x128, 8 warps (warp 64x32). Dyn smem 81920B.
// SPLIT_OUT: write Ch/Cl bf16 split; else fp32 Cf.
// =====================================================================
template<bool SPLIT_OUT>
__global__ void __launch_bounds__(256)
gemm_s(const uint16_t* __restrict__ Ahg, const uint16_t* __restrict__ Alg,
       const uint16_t* __restrict__ Whg, const uint16_t* __restrict__ Wlg,
       const float* __restrict__ bias,
       uint16_t* __restrict__ Ch, uint16_t* __restrict__ Cl,
       float* __restrict__ Cf)
{
    extern __shared__ __align__(16) char sm[];
    const uint32_t sb = smem_u32(sm);
    const int tid = threadIdx.x, wid = tid >> 5, lane = tid & 31;
    const int m0 = blockIdx.x * 128, n0 = blockIdx.y * 128;
    const int wm = (wid & 1) * 64, wn = (wid >> 1) * 32;

    float acc[4][4][4] = {};

    // prologue fill stage 0, chunk 0
    {
        #pragma unroll
        for (int i = 0; i < 2; i++) {
            int f = tid + i * 256;
            int r = f >> 2, c8 = (f & 3) * 8;
            uint32_t so = sb + (uint32_t)(r * LDA + c8) * 2;
            size_t ga = (size_t)(m0 + r) * 768 + c8;
            size_t gb = (size_t)(n0 + r) * 768 + c8;
            cp16(so,           Ahg + ga);
            cp16(so + 10240u,  Alg + ga);
            cp16(so + 20480u,  Whg + gb);
            cp16(so + 30720u,  Wlg + gb);
        }
        CP_COMMIT();
    }

    for (int c = 0; c < 24; c++) {
        const int st = c & 1;
        if (c < 23) {
            const int k0 = (c + 1) * 32;
            const uint32_t stb = sb + (uint32_t)(st ^ 1) * 40960u;
            #pragma unroll
            for (int i = 0; i < 2; i++) {
                int f = tid + i * 256;
                int r = f >> 2, c8 = (f & 3) * 8;
                uint32_t so = stb + (uint32_t)(r * LDA + c8) * 2;
                size_t ga = (size_t)(m0 + r) * 768 + k0 + c8;
                size_t gb = (size_t)(n0 + r) * 768 + k0 + c8;
                cp16(so,           Ahg + ga);
                cp16(so + 10240u,  Alg + ga);
                cp16(so + 20480u,  Whg + gb);
                cp16(so + 30720u,  Wlg + gb);
            }
            CP_COMMIT();
            CP_WAIT1();
        } else {
            CP_WAIT0();
        }
        __syncthreads();
        const uint32_t base = sb + (uint32_t)st * 40960u;
        #pragma unroll
        for (int ks = 0; ks < 2; ks++) {
            uint32_t ah[4][4], al[4][4];
            const int arow = wm + (lane & 7) + ((lane >> 3) & 1) * 8;
            const int acol = ks * 16 + (lane >> 4) * 8;
            #pragma unroll
            for (int mt = 0; mt < 4; mt++) {
                uint32_t off = (uint32_t)((arow + mt * 16) * LDA + acol) * 2;
                ldm_x4(ah[mt], base + off);
                ldm_x4(al[mt], base + 10240u + off);
            }
            const int brow = wn + (lane & 7);
            const int bcol = ks * 16 + ((lane >> 3) & 1) * 8;
            #pragma unroll
            for (int nt = 0; nt < 4; nt++) {
                uint32_t off = (uint32_t)((brow + nt * 8) * LDA + bcol) * 2;
                uint32_t bh2[2], bl2[2];
                ldm_x2(bh2, base + 20480u + off);
                ldm_x2(bl2, base + 30720u + off);
                #pragma unroll
                for (int mt = 0; mt < 4; mt++) {
                    mma_bf16(acc[mt][nt], ah[mt], bh2);
                    mma_bf16(acc[mt][nt], ah[mt], bl2);
                    mma_bf16(acc[mt][nt], al[mt], bh2);
                }
            }
        }
        __syncthreads();
    }

    #pragma unroll
    for (int mt = 0; mt < 4; mt++) {
        const int m = m0 + wm + mt * 16 + (lane >> 2);
        #pragma unroll
        for (int nt = 0; nt < 4; nt++) {
            const int n = n0 + wn + nt * 8 + (lane & 3) * 2;
            float2 bv = *(const float2*)&bias[n];
            float f0 = acc[mt][nt][0] + bv.x, f1 = acc[mt][nt][1] + bv.y;
            float f2 = acc[mt][nt][2] + bv.x, f3 = acc[mt][nt][3] + bv.y;
            if (SPLIT_OUT) {
                uint32_t hi, lo;
                split2(f0, f1, hi, lo);
                *(uint32_t*)&Ch[(size_t)m * 768 + n] = hi;
                *(uint32_t*)&Cl[(size_t)m * 768 + n] = lo;
                split2(f2, f3, hi, lo);
                *(uint32_t*)&Ch[(size_t)(m + 8) * 768 + n] = hi;
                *(uint32_t*)&Cl[(size_t)(m + 8) * 768 + n] = lo;
            } else {
                *(float2*)&Cf[(size_t)m * 768 + n]       = make_float2(f0, f1);
                *(float2*)&Cf[(size_t)(m + 8) * 768 + n] = make_float2(f2, f3);
            }
        }
    }
}

// =====================================================================
// Scores: attn = 0.125 * Q.K^T for kt<=qt; zeros else. Pre-split Q/K,
// one-shot cp.async (K=64). Tile 128x128. Dyn smem 73728B.
// =====================================================================
__global__ void __launch_bounds__(256)
scores_s(const uint16_t* __restrict__ Qh, const uint16_t* __restrict__ Ql,
         const uint16_t* __restrict__ Kh, const uint16_t* __restrict__ Kl,
         float* __restrict__ attn)
{
    const int qt = blockIdx.x, kt = blockIdx.y, bh = blockIdx.z;
    const int q0 = qt * 128, k0 = kt * 128;
    const int tid = threadIdx.x;

    if (kt > qt) {
        float4 z = make_float4(0.f, 0.f, 0.f, 0.f);
        float4* o4 = (float4*)(attn + ((size_t)bh * S_ + q0) * S_ + k0);
        #pragma unroll
        for (int i = 0; i < 16; i++) {
            int f = tid + i * 256;
            int r = f >> 5, c = f & 31;
            o4[(size_t)r * (S_ / 4) + c] = z;
        }
        return;
    }

    extern __shared__ __align__(16) char sm[];
    const uint32_t sb = smem_u32(sm);
    const int wid = tid >> 5, lane = tid & 31;
    const int b = bh / N_HEADS, h = bh % N_HEADS;
    const int wm = (wid & 1) * 64, wn = (wid >> 1) * 32;
    const size_t qbase = (size_t)(b * S_ + q0) * 768 + h * 64;
    const size_t kbase = (size_t)(b * S_ + k0) * 768 + h * 64;

    #pragma unroll
    for (int i = 0; i < 4; i++) {
        int f = tid + i * 256;
        int r = f >> 3, c8 = (f & 7) * 8;
        uint32_t so = sb + (uint32_t)(r * LDV + c8) * 2;
        size_t gq = qbase + (size_t)r * 768 + c8;
        size_t gk = kbase + (size_t)r * 768 + c8;
        cp16(so,           Qh + gq);
        cp16(so + 18432u,  Ql + gq);
        cp16(so + 36864u,  Kh + gk);
        cp16(so + 55296u,  Kl + gk);
    }
    CP_COMMIT(); CP_WAIT0();
    __syncthreads();

    float acc[4][4][4] = {};
    #pragma unroll
    for (int ks = 0; ks < 4; ks++) {
        uint32_t ah[4][4], al[4][4];
        const int arow = wm + (lane & 7) + ((lane >> 3) & 1) * 8;
        const int acol = ks * 16 + (lane >> 4) * 8;
        #pragma unroll
        for (int mt = 0; mt < 4; mt++) {
            uint32_t off = (uint32_t)((arow + mt * 16) * LDV + acol) * 2;
            ldm_x4(ah[mt], sb + off);
            ldm_x4(al[mt], sb + 18432u + off);
        }
        const int brow = wn + (lane & 7);
        const int bcol = ks * 16 + ((lane >> 3) & 1) * 8;
        #pragma unroll
        for (int nt = 0; nt < 4; nt++) {
            uint32_t off = (uint32_t)((brow + nt * 8) * LDV + bcol) * 2;
            uint32_t bh2[2], bl2[2];
            ldm_x2(bh2, sb + 36864u + off);
            ldm_x2(bl2, sb + 55296u + off);
            #pragma unroll
            for (int mt = 0; mt < 4; mt++) {
                mma_bf16(acc[mt][nt], ah[mt], bh2);
                mma_bf16(acc[mt][nt], ah[mt], bl2);
                mma_bf16(acc[mt][nt], al[mt], bh2);
            }
        }
    }
    #pragma unroll
    for (int mt = 0; mt < 4; mt++) {
        const int qrow = q0 + wm + mt * 16 + (lane >> 2);
        #pragma unroll
        for (int nt = 0; nt < 4; nt++) {
            const int kcol = k0 + wn + nt * 8 + (lane & 3) * 2;
            float* op0 = attn + ((size_t)bh * S_ + qrow) * S_ + kcol;
            float* op1 = attn + ((size_t)bh * S_ + qrow + 8) * S_ + kcol;
            *(float2*)op0 = make_float2(acc[mt][nt][0] * 0.125f, acc[mt][nt][1] * 0.125f);
            *(float2*)op1 = make_float2(acc[mt][nt][2] * 0.125f, acc[mt][nt][3] * 0.125f);
        }
    }
}

// =====================================================================
// Row softmax over cols [0, (qt+1)*128); causal mask inside.
// =====================================================================
__global__ void softmax_kernel(float* __restrict__ attn)
{
    const int q  = blockIdx.x;
    const int bh = blockIdx.y;
    const int n4 = ((q >> 7) + 1) * 32;
    float4* row4 = (float4*)(attn + ((size_t)bh * S_ + q) * S_);
    const int tid = threadIdx.x;
    const int lane = tid & 31, wid = tid >> 5;
    __shared__ float red[8];

    float4 v[2];
    int cnt = 0;
    float m = -INFINITY;
    for (int i = tid; i < n4; i += 256) {
        float4 t = row4[i];
        int c = i * 4;
        t.x = (c + 0 <= q) ? t.x : -INFINITY;
        t.y = (c + 1 <= q) ? t.y : -INFINITY;
        t.z = (c + 2 <= q) ? t.z : -INFINITY;
        t.w = (c + 3 <= q) ? t.w : -INFINITY;
        m = fmaxf(m, fmaxf(fmaxf(t.x, t.y), fmaxf(t.z, t.w)));
        v[cnt++] = t;
    }
    #pragma unroll
    for (int s = 16; s > 0; s >>= 1)
        m = fmaxf(m, __shfl_xor_sync(0xffffffff, m, s));
    if (lane == 0) red[wid] = m;
    __syncthreads();
    m = fmaxf(fmaxf(fmaxf(red[0], red[1]), fmaxf(red[2], red[3])),
              fmaxf(fmaxf(red[4], red[5]), fmaxf(red[6], red[7])));
    __syncthreads();

    float sum = 0.f;
    for (int j = 0; j < cnt; j++) {
        float4 t = v[j];
        t.x = __expf(t.x - m); t.y = __expf(t.y - m);
        t.z = __expf(t.z - m); t.w = __expf(t.w - m);
        sum += t.x + t.y + t.z + t.w;
        v[j] = t;
    }
    #pragma unroll
    for (int s = 16; s > 0; s >>= 1)
        sum += __shfl_xor_sync(0xffffffff, sum, s);
    if (lane == 0) red[wid] = sum;
    __syncthreads();
    sum = red[0] + red[1] + red[2] + red[3] + red[4] + red[5] + red[6] + red[7];
    const float inv = 1.0f / sum;

    for (int j = 0; j < cnt; j++) {
        float4 t = v[j];
        t.x *= inv; t.y *= inv; t.z *= inv; t.w *= inv;
        row4[tid + j * 256] = t;
    }
}

// =====================================================================
// PV: O = P @ V. P fp32 (split on the fly), V pre-split (cp.async).
// Tile 128(q)x64(d), K-chunks 32 up to (qt+1)*128. Writes split O.
// 8 warps, warp 32x32. grid (S/128, B*H), heavy q-tiles first.
// =====================================================================
__global__ void __launch_bounds__(256)
pv_s(const float* __restrict__ attn,
     const uint16_t* __restrict__ Vhg, const uint16_t* __restrict__ Vlg,
     uint16_t* __restrict__ Oh, uint16_t* __restrict__ Ol)
{
    __shared__ __align__(16) uint16_t Ph[128][LDA], Pl[128][LDA];
    __shared__ __align__(16) uint16_t Vh_s[32][LDV], Vl_s[32][LDV];
    const int tid = threadIdx.x, wid = tid >> 5, lane = tid & 31;
    const int qt = gridDim.x - 1 - blockIdx.x;
    const int bh = blockIdx.y;
    const int b = bh / N_HEADS, h = bh % N_HEADS;
    const int q0 = qt * 128;
    const int wm = (wid & 3) * 32, wn = (wid >> 2) * 32;
    const uint32_t pHb = smem_u32(Ph), pLb = smem_u32(Pl);
    const uint32_t vHb = smem_u32(Vh_s), vLb = smem_u32(Vl_s);

    const float* Arow = attn + ((size_t)bh * S_ + q0) * S_;
    const size_t vbase = (size_t)(b * S_) * 768 + h * 64;

    float acc[2][4][4] = {};
    const int n_chunks = 4 * (qt + 1);

    for (int c = 0; c < n_chunks; c++) {
        const int k0 = c * 32;
        // V chunk via cp.async (32 rows x 64 halves = 256 chunks/array)
        {
            int r = tid >> 3, c8 = (tid & 7) * 8;
            uint32_t so = (uint32_t)(r * LDV + c8) * 2;
            size_t gv = vbase + (size_t)(k0 + r) * 768 + c8;
            cp16(vHb + so, Vhg + gv);
            cp16(vLb + so, Vlg + gv);
            CP_COMMIT();
        }
        // P chunk: fp32 load + split
        #pragma unroll
        for (int i = 0; i < 4; i++) {
            int f = tid + i * 256;
            int r = f >> 3, c4 = (f & 7) * 4;
            uint2 hi, lo;
            split4(*(const float4*)&Arow[(size_t)r * S_ + k0 + c4], hi, lo);
            *(uint2*)&Ph[r][c4] = hi; *(uint2*)&Pl[r][c4] = lo;
        }
        CP_WAIT0();
        __syncthreads();
        #pragma unroll
        for (int ks = 0; ks < 2; ks++) {
            uint32_t ph[2][4], pl[2][4];
            const int arow = wm + (lane & 7) + ((lane >> 3) & 1) * 8;
            const int acol = ks * 16 + (lane >> 4) * 8;
            #pragma unroll
            for (int mt = 0; mt < 2; mt++) {
                uint32_t off = (uint32_t)((arow + mt * 16) * LDA + acol) * 2;
                ldm_x4(ph[mt], pHb + off);
                ldm_x4(pl[mt], pLb + off);
            }
            const int krow = ks * 16 + ((lane >> 3) & 1) * 8 + (lane & 7);
            #pragma unroll
            for (int nt = 0; nt < 4; nt++) {
                uint32_t off = (uint32_t)(krow * LDV + wn + nt * 8) * 2;
                uint32_t vh2[2], vl2[2];
                ldm_x2_trans(vh2, vHb + off);
                ldm_x2_trans(vl2, vLb + off);
                #pragma unroll
                for (int mt = 0; mt < 2; mt++) {
                    mma_bf16(acc[mt][nt], ph[mt], vh2);
                    mma_bf16(acc[mt][nt], ph[mt], vl2);
                    mma_bf16(acc[mt][nt], pl[mt], vh2);
                }
            }
        }
        __syncthreads();
    }
    #pragma unroll
    for (int mt = 0; mt < 2; mt++) {
        const int qrow = q0 + wm + mt * 16 + (lane >> 2);
        const size_t r0 = (size_t)(b * S_ + qrow) * 768 + h * 64;
        const size_t r1 = (size_t)(b * S_ + qrow + 8) * 768 + h * 64;
        #pragma unroll
        for (int nt = 0; nt < 4; nt++) {
            const int n = wn + nt * 8 + (lane & 3) * 2;
            uint32_t hi, lo;
            split2(acc[mt][nt][0], acc[mt][nt][1], hi, lo);
            *(uint32_t*)&Oh[r0 + n] = hi;
            *(uint32_t*)&Ol[r0 + n] = lo;
            split2(acc[mt][nt][2], acc[mt][nt][3], hi, lo);
            *(uint32_t*)&Oh[r1 + n] = hi;
            *(uint32_t*)&Ol[r1 + n] = lo;
        }
    }
}

// =====================================================================
// Residual + LayerNorm, float4, 192 threads.
// =====================================================================
__global__ void ln_kernel(const float* __restrict__ resid,
                          const float* __restrict__ P,
                          const float* __restrict__ gamma,
                          const float* __restrict__ beta,
                          float* __restrict__ out)
{
    const int m = blockIdx.x;
    const int tid = threadIdx.x;
    const int lane = tid & 31, wid = tid >> 5;
    __shared__ float red[6];

    const float4* r4 = (const float4*)(resid + (size_t)m * D_MODEL);
    const float4* p4 = (const float4*)(P + (size_t)m * D_MODEL);
    float4 a = r4[tid], b = p4[tid];
    float4 x = make_float4(a.x + b.x, a.y + b.y, a.z + b.z, a.w + b.w);

    float s = x.x + x.y + x.z + x.w;
    #pragma unroll
    for (int sh = 16; sh > 0; sh >>= 1)
        s += __shfl_xor_sync(0xffffffff, s, sh);
    if (lane == 0) red[wid] = s;
    __syncthreads();
    s = red[0] + red[1] + red[2] + red[3] + red[4] + red[5];
    const float mu = s * (1.0f / D_MODEL);
    __syncthreads();

    float4 d = make_float4(x.x - mu, x.y - mu, x.z - mu, x.w - mu);
    float v = d.x * d.x + d.y * d.y + d.z * d.z + d.w * d.w;
    #pragma unroll
    for (int sh = 16; sh > 0; sh >>= 1)
        v += __shfl_xor_sync(0xffffffff, v, sh);
    if (lane == 0) red[wid] = v;
    __syncthreads();
    v = red[0] + red[1] + red[2] + red[3] + red[4] + red[5];
    const float rstd = rsqrtf(v * (1.0f / D_MODEL) + LN_EPS);

    float4 g = ((const float4*)gamma)[tid];
    float4 be = ((const float4*)beta)[tid];
    float4 o = make_float4(d.x * rstd * g.x + be.x,
                           d.y * rstd * g.y + be.y,
                           d.z * rstd * g.z + be.z,
                           d.w * rstd * g.w + be.w);
    ((float4*)(out + (size_t)m * D_MODEL))[tid] = o;
}

// =====================================================================
extern "C" void kernel_launch(void* const* d_in, const int* in_sizes, int n_in,
                              void* d_out, int out_size)
{
    const float* q     = (const float*)d_in[0];
    const float* k     = (const float*)d_in[1];
    const float* v     = (const float*)d_in[2];
    const float* Wq    = (const float*)d_in[4];
    const float* bq    = (const float*)d_in[5];
    const float* Wk    = (const float*)d_in[6];
    const float* bk    = (const float*)d_in[7];
    const float* Wv    = (const float*)d_in[8];
    const float* bv    = (const float*)d_in[9];
    const float* Wo    = (const float*)d_in[10];
    const float* bo    = (const float*)d_in[11];
    const float* gamma = (const float*)d_in[12];
    const float* beta  = (const float*)d_in[13];

    float* out  = (float*)d_out;
    float* attn = out + (size_t)M_TOT * D_MODEL;

    uint16_t *inqh, *inql, *inkh, *inkl, *invh, *invl;
    uint16_t *wqh, *wql, *wkh, *wkl, *wvh, *wvl, *woh, *wol;
    uint16_t *Qh, *Ql, *Kh, *Kl, *Vh, *Vl, *Oh, *Ol;
    float* Pp;
    cudaGetSymbolAddress((void**)&inqh, g_inqh); cudaGetSymbolAddress((void**)&inql, g_inql);
    cudaGetSymbolAddress((void**)&inkh, g_inkh); cudaGetSymbolAddress((void**)&inkl, g_inkl);
    cudaGetSymbolAddress((void**)&invh, g_invh); cudaGetSymbolAddress((void**)&invl, g_invl);
    cudaGetSymbolAddress((void**)&wqh, g_wqh); cudaGetSymbolAddress((void**)&wql, g_wql);
    cudaGetSymbolAddress((void**)&wkh, g_wkh); cudaGetSymbolAddress((void**)&wkl, g_wkl);
    cudaGetSymbolAddress((void**)&wvh, g_wvh); cudaGetSymbolAddress((void**)&wvl, g_wvl);
    cudaGetSymbolAddress((void**)&woh, g_woh); cudaGetSymbolAddress((void**)&wol, g_wol);
    cudaGetSymbolAddress((void**)&Qh, g_Qh); cudaGetSymbolAddress((void**)&Ql, g_Ql);
    cudaGetSymbolAddress((void**)&Kh, g_Kh); cudaGetSymbolAddress((void**)&Kl, g_Kl);
    cudaGetSymbolAddress((void**)&Vh, g_Vh); cudaGetSymbolAddress((void**)&Vl, g_Vl);
    cudaGetSymbolAddress((void**)&Oh, g_Oh); cudaGetSymbolAddress((void**)&Ol, g_Ol);
    cudaGetSymbolAddress((void**)&Pp, g_P);

    const int SMEM_GEMM   = 81920;
    const int SMEM_SCORES = 73728;
    cudaFuncSetAttribute(gemm_s<true>,  cudaFuncAttributeMaxDynamicSharedMemorySize, SMEM_GEMM);
    cudaFuncSetAttribute(gemm_s<false>, cudaFuncAttributeMaxDynamicSharedMemorySize, SMEM_GEMM);
    cudaFuncSetAttribute(scores_s,      cudaFuncAttributeMaxDynamicSharedMemorySize, SMEM_SCORES);

    // pre-split inputs + weights
    split_kernel<<<3072, 256>>>((const float4*)q, (uint2*)inqh, (uint2*)inql);
    split_kernel<<<3072, 256>>>((const float4*)k, (uint2*)inkh, (uint2*)inkl);
    split_kernel<<<3072, 256>>>((const float4*)v, (uint2*)invh, (uint2*)invl);
    split_kernel<<<576, 256>>>((const float4*)Wq, (uint2*)wqh, (uint2*)wql);
    split_kernel<<<576, 256>>>((const float4*)Wk, (uint2*)wkh, (uint2*)wkl);
    split_kernel<<<576, 256>>>((const float4*)Wv, (uint2*)wvh, (uint2*)wvl);
    split_kernel<<<576, 256>>>((const float4*)Wo, (uint2*)woh, (uint2*)wol);

    dim3 gProj(M_TOT / 128, D_MODEL / 128);
    gemm_s<true><<<gProj, 256, SMEM_GEMM>>>(inqh, inql, wqh, wql, bq, Qh, Ql, nullptr);
    gemm_s<true><<<gProj, 256, SMEM_GEMM>>>(inkh, inkl, wkh, wkl, bk, Kh, Kl, nullptr);
    gemm_s<true><<<gProj, 256, SMEM_GEMM>>>(invh, invl, wvh, wvl, bv, Vh, Vl, nullptr);

    dim3 gScores(S_ / 128, S_ / 128, B_ * N_HEADS);
    scores_s<<<gScores, 256, SMEM_SCORES>>>(Qh, Ql, Kh, Kl, attn);

    dim3 gSoft(S_, B_ * N_HEADS);
    softmax_kernel<<<gSoft, 256>>>(attn);

    dim3 gPV(S_ / 128, B_ * N_HEADS);
    pv_s<<<gPV, 256>>>(attn, Vh, Vl, Oh, Ol);

    gemm_s<false><<<gProj, 256, SMEM_GEMM>>>(Oh, Ol, woh, wol, bo, nullptr, nullptr, Pp);

    ln_kernel<<<M_TOT, 192>>>(q, Pp, gamma, beta, out);
}